// round 5
// baseline (speedup 1.0000x reference)
#include <cuda_runtime.h>
#include <cuda_bf16.h>
#include <cstdint>

#define BATCH 32768
#define HD 512

// ---------------- device scratch (no allocations allowed) ----------------
__device__ int8_t g_xq1[BATCH * HD], g_xq2[BATCH * HD];
__device__ int8_t g_uq1[BATCH * HD], g_uq2[BATCH * HD];
__device__ int8_t g_tq1[BATCH * HD], g_tq2[BATCH * HD];
__device__ float g_sx[BATCH], g_su[BATCH], g_st[BATCH];

__device__ int8_t g_wq_in1[HD * HD], g_wq_in2[HD * HD];
__device__ int8_t g_wq_cat1[4 * HD * HD], g_wq_cat2[4 * HD * HD];
__device__ int8_t g_wq_h1[HD * HD], g_wq_h2[HD * HD];
__device__ float g_swin[HD], g_swcat[4 * HD], g_swh[HD];

__device__ float g_pre[BATCH * HD];               // GEMM1 out, reused for GEMM3 out
__device__ float g_P[(size_t)BATCH * 4 * HD];     // z_pre | k | v | d_pre
__device__ float g_z[BATCH * HD];

// ---------------- helpers ----------------
__device__ __forceinline__ uint32_t smem_u32(const void* p) {
    return (uint32_t)__cvta_generic_to_shared(p);
}
__device__ __forceinline__ void cp16(uint32_t dst, const void* src) {
    asm volatile("cp.async.cg.shared.global [%0], [%1], 16;\n" :: "r"(dst), "l"(src));
}
__device__ __forceinline__ void ldm4(uint32_t (&r)[4], uint32_t addr) {
    asm volatile("ldmatrix.sync.aligned.m8n8.x4.shared.b16 {%0,%1,%2,%3}, [%4];\n"
                 : "=r"(r[0]), "=r"(r[1]), "=r"(r[2]), "=r"(r[3]) : "r"(addr));
}
__device__ __forceinline__ void imma(int (&d)[4], const uint32_t (&a)[4],
                                     uint32_t b0, uint32_t b1) {
    asm volatile("mma.sync.aligned.m16n8k32.row.col.s32.s8.s8.s32 "
                 "{%0,%1,%2,%3}, {%4,%5,%6,%7}, {%8,%9}, {%0,%1,%2,%3};\n"
                 : "+r"(d[0]), "+r"(d[1]), "+r"(d[2]), "+r"(d[3])
                 : "r"(a[0]), "r"(a[1]), "r"(a[2]), "r"(a[3]), "r"(b0), "r"(b1));
}
__device__ __forceinline__ float sigf(float x) { return 1.0f / (1.0f + __expf(-x)); }

// quantize 4 floats (already scaled domain) into 2-digit int8
__device__ __forceinline__ void q4store(int8_t* d1, int8_t* d2, size_t idx, float S,
                                        float v0, float v1, float v2, float v3) {
    char4 c1, c2;
    {
        float q = rintf(v0 * S); float h = rintf(q * 0.0078125f);
        c1.x = (signed char)(int)h; c2.x = (signed char)((int)q - (((int)h) << 7));
    }
    {
        float q = rintf(v1 * S); float h = rintf(q * 0.0078125f);
        c1.y = (signed char)(int)h; c2.y = (signed char)((int)q - (((int)h) << 7));
    }
    {
        float q = rintf(v2 * S); float h = rintf(q * 0.0078125f);
        c1.z = (signed char)(int)h; c2.z = (signed char)((int)q - (((int)h) << 7));
    }
    {
        float q = rintf(v3 * S); float h = rintf(q * 0.0078125f);
        c1.w = (signed char)(int)h; c2.w = (signed char)((int)q - (((int)h) << 7));
    }
    *reinterpret_cast<char4*>(d1 + idx) = c1;
    *reinterpret_cast<char4*>(d2 + idx) = c2;
}

__device__ __forceinline__ float warp_max(float v) {
#pragma unroll
    for (int o = 16; o; o >>= 1) v = fmaxf(v, __shfl_xor_sync(0xffffffffu, v, o));
    return v;
}

// ---------------- weight prep: per-column max + 2-digit int8, transposed ----------------
__global__ void prep_wq(const float* __restrict__ W_in, const float* __restrict__ W_z,
                        const float* __restrict__ W_k, const float* __restrict__ W_v,
                        const float* __restrict__ W_d, const float* __restrict__ W_h) {
    int col = blockIdx.x;           // 0..3071
    int tid = threadIdx.x;          // 128
    const float* W; int8_t *D1, *D2; float* sp; int n, drow, sidx;
    if (col < 512) {
        W = W_in; D1 = g_wq_in1; D2 = g_wq_in2; sp = g_swin; n = col; drow = col; sidx = col;
    } else if (col < 2560) {
        int cc = col - 512; int m = cc >> 9; n = cc & 511;
        W = (m == 0) ? W_z : (m == 1) ? W_k : (m == 2) ? W_v : W_d;
        D1 = g_wq_cat1; D2 = g_wq_cat2; sp = g_swcat; drow = cc; sidx = cc;
    } else {
        W = W_h; D1 = g_wq_h1; D2 = g_wq_h2; sp = g_swh; n = col - 2560; drow = n; sidx = n;
    }
    float v[4]; float mx = 0.f;
#pragma unroll
    for (int j = 0; j < 4; j++) {
        v[j] = W[(size_t)(tid + 128 * j) * HD + n];
        mx = fmaxf(mx, fabsf(v[j]));
    }
    __shared__ float red[4];
    mx = warp_max(mx);
    if ((tid & 31) == 0) red[tid >> 5] = mx;
    __syncthreads();
    mx = fmaxf(fmaxf(red[0], red[1]), fmaxf(red[2], red[3]));
    mx = fmaxf(mx, 1e-30f);
    float S = 16256.f / mx;
    if (tid == 0) sp[sidx] = mx / 16256.f;
#pragma unroll
    for (int j = 0; j < 4; j++) {
        float q = rintf(v[j] * S);
        float h = rintf(q * 0.0078125f);
        int a1 = (int)h, a2 = (int)q - (a1 << 7);
        D1[(size_t)drow * HD + tid + 128 * j] = (int8_t)a1;
        D2[(size_t)drow * HD + tid + 128 * j] = (int8_t)a2;
    }
}

// ---------------- quantize x (per-row scale) ----------------
__global__ void quant_x(const float* __restrict__ x) {
    int row = blockIdx.x * 8 + (threadIdx.x >> 5);
    int lane = threadIdx.x & 31;
    const float* p = x + (size_t)row * HD;
    float v[16]; float mx = 0.f;
#pragma unroll
    for (int i = 0; i < 4; i++) {
        int c = i * 128 + lane * 4;
        float4 x4 = *reinterpret_cast<const float4*>(p + c);
        v[i * 4 + 0] = x4.x; v[i * 4 + 1] = x4.y; v[i * 4 + 2] = x4.z; v[i * 4 + 3] = x4.w;
        mx = fmaxf(mx, fmaxf(fmaxf(fabsf(x4.x), fabsf(x4.y)), fmaxf(fabsf(x4.z), fabsf(x4.w))));
    }
    mx = fmaxf(warp_max(mx), 1e-30f);
    float S = 16256.f / mx;
    if (lane == 0) g_sx[row] = mx / 16256.f;
#pragma unroll
    for (int i = 0; i < 4; i++) {
        size_t idx = (size_t)row * HD + i * 128 + lane * 4;
        q4store(g_xq1, g_xq2, idx, S, v[i * 4], v[i * 4 + 1], v[i * 4 + 2], v[i * 4 + 3]);
    }
}

// ---------------- int8 split GEMM: C[M,N] = dequant(A) @ dequant(W) ----------------
#define GBM 128
#define GBN 64
#define GST 48                                 // smem row stride bytes (conflict-free)
#define A_T (GBM * GST)                        // 6144
#define B_T (GBN * GST)                        // 3072
#define STAGEB (2 * A_T + 2 * B_T)             // 18432
#define SM_TOT (3 * STAGEB)                    // 55296

template <int WHICH>
__global__ void __launch_bounds__(256, 2) gemm_i8() {
    const int8_t* A1p = (WHICH == 0) ? g_xq1 : (WHICH == 1) ? g_uq1 : g_tq1;
    const int8_t* A2p = (WHICH == 0) ? g_xq2 : (WHICH == 1) ? g_uq2 : g_tq2;
    const int8_t* B1p = (WHICH == 0) ? g_wq_in1 : (WHICH == 1) ? g_wq_cat1 : g_wq_h1;
    const int8_t* B2p = (WHICH == 0) ? g_wq_in2 : (WHICH == 1) ? g_wq_cat2 : g_wq_h2;
    const float* sa = (WHICH == 0) ? g_sx : (WHICH == 1) ? g_su : g_st;
    const float* sw = (WHICH == 0) ? g_swin : (WHICH == 1) ? g_swcat : g_swh;
    float* C = (WHICH == 1) ? g_P : g_pre;
    const int N = (WHICH == 1) ? 4 * HD : HD;

    extern __shared__ __align__(128) char smm[];
    const int tid = threadIdx.x;
    const int warp = tid >> 5, lane = tid & 31;
    const int m0 = blockIdx.y * GBM;
    const int n0 = blockIdx.x * GBN;
    const int wm = (warp >> 1) * 32;   // 4 warps along M
    const int wn = (warp & 1) * 32;    // 2 warps along N

    int accM[2][4][4], accX[2][4][4];
#pragma unroll
    for (int a = 0; a < 2; a++)
#pragma unroll
        for (int b = 0; b < 4; b++)
#pragma unroll
            for (int c = 0; c < 4; c++) { accM[a][b][c] = 0; accX[a][b][c] = 0; }

    // loader: A digits: chunk=tid (row=tid>>1, 16B half tid&1); B: digit=tid>>7, chunk tid&127
    const int arow = tid >> 1, acb = (tid & 1) * 16;
    const int bdg = tid >> 7, bc = tid & 127;
    const int brow = bc >> 1, bcb = (bc & 1) * 16;
    const int8_t* Bdp = bdg ? B2p : B1p;

    auto load_stage = [&](int s) {
        char* base = smm + (s % 3) * STAGEB;
        const int k0 = s * 32;
        cp16(smem_u32(base + arow * GST + acb),
             A1p + (size_t)(m0 + arow) * HD + k0 + acb);
        cp16(smem_u32(base + A_T + arow * GST + acb),
             A2p + (size_t)(m0 + arow) * HD + k0 + acb);
        cp16(smem_u32(base + 2 * A_T + bdg * B_T + brow * GST + bcb),
             Bdp + (size_t)(n0 + brow) * HD + k0 + bcb);
        asm volatile("cp.async.commit_group;\n");
    };

    load_stage(0);
    load_stage(1);

    for (int s = 0; s < 16; ++s) {
        if (s == 15) asm volatile("cp.async.wait_group 0;\n");
        else         asm volatile("cp.async.wait_group 1;\n");
        __syncthreads();
        if (s + 2 < 16) load_stage(s + 2);

        char* base = smm + (s % 3) * STAGEB;
        uint32_t a1f[2][4], a2f[2][4], b1f[2][4], b2f[2][4];
#pragma unroll
        for (int mi = 0; mi < 2; mi++) {
            uint32_t ad = smem_u32(base + (wm + mi * 16 + (lane & 15)) * GST + ((lane >> 4) << 4));
            ldm4(a1f[mi], ad);
            ldm4(a2f[mi], ad + A_T);
        }
#pragma unroll
        for (int j = 0; j < 2; j++) {
            uint32_t bd = smem_u32(base + 2 * A_T + (wn + j * 16 + (lane & 15)) * GST + ((lane >> 4) << 4));
            ldm4(b1f[j], bd);
            ldm4(b2f[j], bd + B_T);
        }
#pragma unroll
        for (int mi = 0; mi < 2; mi++)
#pragma unroll
            for (int j = 0; j < 2; j++)
#pragma unroll
                for (int t = 0; t < 2; t++) {
                    const int nj = j * 2 + t;
                    imma(accM[mi][nj], a1f[mi], b1f[j][t], b1f[j][t + 2]);
                    imma(accX[mi][nj], a1f[mi], b2f[j][t], b2f[j][t + 2]);
                    imma(accX[mi][nj], a2f[mi], b1f[j][t], b1f[j][t + 2]);
                }
    }

    // epilogue: combine digits, apply row/col scales, write fp32
#pragma unroll
    for (int mi = 0; mi < 2; mi++) {
        int r = m0 + wm + mi * 16 + (lane >> 2);
        float saA = sa[r] ;
        float saB = sa[r + 8];
#pragma unroll
        for (int nj = 0; nj < 4; nj++) {
            int c = n0 + wn + nj * 8 + (lane & 3) * 2;
            float sw0 = sw[c], sw1 = sw[c + 1];
            float v00 = (16384.f * (float)accM[mi][nj][0] + 128.f * (float)accX[mi][nj][0]) * saA * sw0;
            float v01 = (16384.f * (float)accM[mi][nj][1] + 128.f * (float)accX[mi][nj][1]) * saA * sw1;
            float v10 = (16384.f * (float)accM[mi][nj][2] + 128.f * (float)accX[mi][nj][2]) * saB * sw0;
            float v11 = (16384.f * (float)accM[mi][nj][3] + 128.f * (float)accX[mi][nj][3]) * saB * sw1;
            *reinterpret_cast<float2*>(&C[(size_t)r * N + c]) = make_float2(v00, v01);
            *reinterpret_cast<float2*>(&C[(size_t)(r + 8) * N + c]) = make_float2(v10, v11);
        }
    }
}

// ---------------- LN over g_pre -> u (quantized 2-digit int8 + row scale) ----------------
__global__ void ln_u_kernel(const float* __restrict__ bias, const float* __restrict__ gamma,
                            const float* __restrict__ beta) {
    int row = blockIdx.x * 8 + (threadIdx.x >> 5);
    int lane = threadIdx.x & 31;
    const float* p = g_pre + (size_t)row * HD;
    float v[16];
    float sm = 0.f, sq = 0.f;
#pragma unroll
    for (int i = 0; i < 4; i++) {
        int c = i * 128 + lane * 4;
        float4 x4 = *reinterpret_cast<const float4*>(p + c);
        float4 b4 = *reinterpret_cast<const float4*>(bias + c);
        float t0 = x4.x + b4.x, t1 = x4.y + b4.y, t2 = x4.z + b4.z, t3 = x4.w + b4.w;
        v[i * 4 + 0] = t0; v[i * 4 + 1] = t1; v[i * 4 + 2] = t2; v[i * 4 + 3] = t3;
        sm += t0 + t1 + t2 + t3;
        sq += t0 * t0 + t1 * t1 + t2 * t2 + t3 * t3;
    }
#pragma unroll
    for (int o = 16; o; o >>= 1) {
        sm += __shfl_xor_sync(0xffffffffu, sm, o);
        sq += __shfl_xor_sync(0xffffffffu, sq, o);
    }
    float mean = sm * (1.f / HD);
    float inv = rsqrtf(fmaxf(sq * (1.f / HD) - mean * mean, 0.f) + 1e-5f);
    float mx = 0.f;
#pragma unroll
    for (int i = 0; i < 4; i++) {
        int c = i * 128 + lane * 4;
        float4 g4 = *reinterpret_cast<const float4*>(gamma + c);
        float4 b4 = *reinterpret_cast<const float4*>(beta + c);
        float u0 = (v[i * 4 + 0] - mean) * inv * g4.x + b4.x;
        float u1 = (v[i * 4 + 1] - mean) * inv * g4.y + b4.y;
        float u2 = (v[i * 4 + 2] - mean) * inv * g4.z + b4.z;
        float u3 = (v[i * 4 + 3] - mean) * inv * g4.w + b4.w;
        v[i * 4 + 0] = u0; v[i * 4 + 1] = u1; v[i * 4 + 2] = u2; v[i * 4 + 3] = u3;
        mx = fmaxf(mx, fmaxf(fmaxf(fabsf(u0), fabsf(u1)), fmaxf(fabsf(u2), fabsf(u3))));
    }
    mx = fmaxf(warp_max(mx), 1e-30f);
    float S = 16256.f / mx;
    if (lane == 0) g_su[row] = mx / 16256.f;
#pragma unroll
    for (int i = 0; i < 4; i++) {
        size_t idx = (size_t)row * HD + i * 128 + lane * 4;
        q4store(g_uq1, g_uq2, idx, S, v[i * 4], v[i * 4 + 1], v[i * 4 + 2], v[i * 4 + 3]);
    }
}

// ---------------- epilogue 1: z, s, t(quantized) ----------------
__global__ void epi1_kernel(const float* __restrict__ s_prev, const float* __restrict__ bz,
                            const float* __restrict__ glz, const float* __restrict__ blz,
                            const float* __restrict__ bk, const float* __restrict__ bv,
                            const float* __restrict__ bd, float* __restrict__ out_s) {
    int row = blockIdx.x * 8 + (threadIdx.x >> 5);
    int lane = threadIdx.x & 31;
    const float* Pr = g_P + (size_t)row * (4 * HD);
    float zp[16];
    float sm = 0.f, sq = 0.f;
#pragma unroll
    for (int i = 0; i < 4; i++) {
        int c = i * 128 + lane * 4;
        float4 z4 = *reinterpret_cast<const float4*>(Pr + c);
        float4 b4 = *reinterpret_cast<const float4*>(bz + c);
        float t0 = z4.x + b4.x, t1 = z4.y + b4.y, t2 = z4.z + b4.z, t3 = z4.w + b4.w;
        zp[i * 4 + 0] = t0; zp[i * 4 + 1] = t1; zp[i * 4 + 2] = t2; zp[i * 4 + 3] = t3;
        sm += t0 + t1 + t2 + t3;
        sq += t0 * t0 + t1 * t1 + t2 * t2 + t3 * t3;
    }
#pragma unroll
    for (int o = 16; o; o >>= 1) {
        sm += __shfl_xor_sync(0xffffffffu, sm, o);
        sq += __shfl_xor_sync(0xffffffffu, sq, o);
    }
    float mean = sm * (1.f / HD);
    float inv = rsqrtf(fmaxf(sq * (1.f / HD) - mean * mean, 0.f) + 1e-5f);
    float su = g_su[row];
    float tmax = 0.f;
#pragma unroll
    for (int i = 0; i < 4; i++) {
        int c = i * 128 + lane * 4;
        size_t idx = (size_t)row * HD + c;
        float4 g4 = *reinterpret_cast<const float4*>(glz + c);
        float4 bb4 = *reinterpret_cast<const float4*>(blz + c);
        float z0 = sigf((zp[i * 4 + 0] - mean) * inv * g4.x + bb4.x);
        float z1 = sigf((zp[i * 4 + 1] - mean) * inv * g4.y + bb4.y);
        float z2 = sigf((zp[i * 4 + 2] - mean) * inv * g4.z + bb4.z);
        float z3 = sigf((zp[i * 4 + 3] - mean) * inv * g4.w + bb4.w);
        *reinterpret_cast<float4*>(&g_z[idx]) = make_float4(z0, z1, z2, z3);

        float4 k4 = *reinterpret_cast<const float4*>(Pr + HD + c);
        float4 bk4 = *reinterpret_cast<const float4*>(bk + c);
        float4 v4 = *reinterpret_cast<const float4*>(Pr + 2 * HD + c);
        float4 bv4 = *reinterpret_cast<const float4*>(bv + c);
        float4 d4 = *reinterpret_cast<const float4*>(Pr + 3 * HD + c);
        float4 bd4 = *reinterpret_cast<const float4*>(bd + c);
        float4 sp = *reinterpret_cast<const float4*>(s_prev + idx);

        float kk0 = k4.x + bk4.x, kk1 = k4.y + bk4.y, kk2 = k4.z + bk4.z, kk3 = k4.w + bk4.w;
        float vv0 = v4.x + bv4.x, vv1 = v4.y + bv4.y, vv2 = v4.z + bv4.z, vv3 = v4.w + bv4.w;
        float dc0 = sigf(d4.x + bd4.x), dc1 = sigf(d4.y + bd4.y);
        float dc2 = sigf(d4.z + bd4.z), dc3 = sigf(d4.w + bd4.w);
        float s0 = dc0 * sp.x + kk0 * vv0;
        float s1 = dc1 * sp.y + kk1 * vv1;
        float s2 = dc2 * sp.z + kk2 * vv2;
        float s3 = dc3 * sp.w + kk3 * vv3;
        *reinterpret_cast<float4*>(out_s + idx) = make_float4(s0, s1, s2, s3);

        char4 q1 = *reinterpret_cast<const char4*>(&g_uq1[idx]);
        char4 q2 = *reinterpret_cast<const char4*>(&g_uq2[idx]);
        float t0 = (float)(128 * (int)q1.x + (int)q2.x) * su + s0;
        float t1 = (float)(128 * (int)q1.y + (int)q2.y) * su + s1;
        float t2 = (float)(128 * (int)q1.z + (int)q2.z) * su + s2;
        float t3 = (float)(128 * (int)q1.w + (int)q2.w) * su + s3;
        zp[i * 4 + 0] = t0; zp[i * 4 + 1] = t1; zp[i * 4 + 2] = t2; zp[i * 4 + 3] = t3;
        tmax = fmaxf(tmax, fmaxf(fmaxf(fabsf(t0), fabsf(t1)), fmaxf(fabsf(t2), fabsf(t3))));
    }
    tmax = fmaxf(warp_max(tmax), 1e-30f);
    float S = 16256.f / tmax;
    if (lane == 0) g_st[row] = tmax / 16256.f;
#pragma unroll
    for (int i = 0; i < 4; i++) {
        size_t idx = (size_t)row * HD + i * 128 + lane * 4;
        q4store(g_tq1, g_tq2, idx, S, zp[i * 4], zp[i * 4 + 1], zp[i * 4 + 2], zp[i * 4 + 3]);
    }
}

// ---------------- epilogue 2: h ----------------
__global__ void epi2_kernel(const float* __restrict__ h_prev, const float* __restrict__ bh,
                            const float* __restrict__ glh, const float* __restrict__ blh,
                            float* __restrict__ out_h) {
    int row = blockIdx.x * 8 + (threadIdx.x >> 5);
    int lane = threadIdx.x & 31;
    const float* p = g_pre + (size_t)row * HD;
    float v[16];
    float sm = 0.f, sq = 0.f;
#pragma unroll
    for (int i = 0; i < 4; i++) {
        int c = i * 128 + lane * 4;
        float4 x4 = *reinterpret_cast<const float4*>(p + c);
        float4 b4 = *reinterpret_cast<const float4*>(bh + c);
        float t0 = x4.x + b4.x, t1 = x4.y + b4.y, t2 = x4.z + b4.z, t3 = x4.w + b4.w;
        v[i * 4 + 0] = t0; v[i * 4 + 1] = t1; v[i * 4 + 2] = t2; v[i * 4 + 3] = t3;
        sm += t0 + t1 + t2 + t3;
        sq += t0 * t0 + t1 * t1 + t2 * t2 + t3 * t3;
    }
#pragma unroll
    for (int o = 16; o; o >>= 1) {
        sm += __shfl_xor_sync(0xffffffffu, sm, o);
        sq += __shfl_xor_sync(0xffffffffu, sq, o);
    }
    float mean = sm * (1.f / HD);
    float inv = rsqrtf(fmaxf(sq * (1.f / HD) - mean * mean, 0.f) + 1e-5f);
#pragma unroll
    for (int i = 0; i < 4; i++) {
        int c = i * 128 + lane * 4;
        size_t idx = (size_t)row * HD + c;
        float4 g4 = *reinterpret_cast<const float4*>(glh + c);
        float4 b4 = *reinterpret_cast<const float4*>(blh + c);
        float c0 = tanhf((v[i * 4 + 0] - mean) * inv * g4.x + b4.x);
        float c1 = tanhf((v[i * 4 + 1] - mean) * inv * g4.y + b4.y);
        float c2 = tanhf((v[i * 4 + 2] - mean) * inv * g4.z + b4.z);
        float c3 = tanhf((v[i * 4 + 3] - mean) * inv * g4.w + b4.w);
        float4 z4 = *reinterpret_cast<const float4*>(&g_z[idx]);
        float4 hp = *reinterpret_cast<const float4*>(h_prev + idx);
        float h0 = (1.f - z4.x) * c0 + z4.x * hp.x;
        float h1 = (1.f - z4.y) * c1 + z4.y * hp.y;
        float h2 = (1.f - z4.z) * c2 + z4.z * hp.z;
        float h3 = (1.f - z4.w) * c3 + z4.w * hp.w;
        *reinterpret_cast<float4*>(out_h + idx) = make_float4(h0, h1, h2, h3);
    }
}

// ---------------- launch ----------------
extern "C" void kernel_launch(void* const* d_in, const int* in_sizes, int n_in,
                              void* d_out, int out_size) {
    const float* x       = (const float*)d_in[0];
    const float* h_prev  = (const float*)d_in[1];
    const float* s_prev  = (const float*)d_in[2];
    const float* W_in    = (const float*)d_in[3];
    const float* b_in    = (const float*)d_in[4];
    const float* g_ln_in = (const float*)d_in[5];
    const float* b_ln_in = (const float*)d_in[6];
    const float* g_ln_z  = (const float*)d_in[9];
    const float* b_ln_z  = (const float*)d_in[10];
    const float* g_ln_h  = (const float*)d_in[11];
    const float* b_ln_h  = (const float*)d_in[12];
    const float* W_z     = (const float*)d_in[15];
    const float* b_z     = (const float*)d_in[16];
    const float* W_k     = (const float*)d_in[17];
    const float* b_k     = (const float*)d_in[18];
    const float* W_v     = (const float*)d_in[19];
    const float* b_v     = (const float*)d_in[20];
    const float* W_h     = (const float*)d_in[21];
    const float* b_h     = (const float*)d_in[22];
    const float* W_d     = (const float*)d_in[23];
    const float* b_d     = (const float*)d_in[24];

    float* out_h = (float*)d_out;
    float* out_s = out_h + (size_t)BATCH * HD;

    cudaFuncSetAttribute(gemm_i8<0>, cudaFuncAttributeMaxDynamicSharedMemorySize, SM_TOT);
    cudaFuncSetAttribute(gemm_i8<1>, cudaFuncAttributeMaxDynamicSharedMemorySize, SM_TOT);
    cudaFuncSetAttribute(gemm_i8<2>, cudaFuncAttributeMaxDynamicSharedMemorySize, SM_TOT);

    prep_wq<<<3072, 128>>>(W_in, W_z, W_k, W_v, W_d, W_h);
    quant_x<<<BATCH / 8, 256>>>(x);

    gemm_i8<0><<<dim3(HD / GBN, BATCH / GBM), 256, SM_TOT>>>();
    ln_u_kernel<<<BATCH / 8, 256>>>(b_in, g_ln_in, b_ln_in);

    gemm_i8<1><<<dim3(4 * HD / GBN, BATCH / GBM), 256, SM_TOT>>>();
    epi1_kernel<<<BATCH / 8, 256>>>(s_prev, b_z, g_ln_z, b_ln_z, b_k, b_v, b_d, out_s);

    gemm_i8<2><<<dim3(HD / GBN, BATCH / GBM), 256, SM_TOT>>>();
    epi2_kernel<<<BATCH / 8, 256>>>(h_prev, b_h, g_ln_h, b_ln_h, out_h);
}

// round 6
// speedup vs baseline: 2.7135x; 2.7135x over previous
#include <cuda_runtime.h>
#include <cuda_fp16.h>
#include <cstdint>

#define BATCH 32768
#define HD 512
typedef __half fp16;

// ---------------- device scratch (no allocations allowed) ----------------
__device__ fp16 g_x1[BATCH * HD], g_x2[BATCH * HD];
__device__ fp16 g_u1[BATCH * HD], g_u2[BATCH * HD];
__device__ fp16 g_t1[BATCH * HD], g_t2[BATCH * HD];
__device__ float g_pre[BATCH * HD];               // GEMM1 out, reused for GEMM3 out
__device__ float g_P[(size_t)BATCH * 4 * HD];     // z_pre | k | v | d_pre
__device__ float g_z[BATCH * HD];
__device__ fp16 g_W_in[HD * HD];
__device__ fp16 g_W_cat[4 * HD * HD];
__device__ fp16 g_W_h[HD * HD];

// ---------------- helpers ----------------
__device__ __forceinline__ uint32_t smem_u32(const void* p) {
    return (uint32_t)__cvta_generic_to_shared(p);
}
__device__ __forceinline__ void cp16(uint32_t dst, const void* src) {
    asm volatile("cp.async.cg.shared.global [%0], [%1], 16;\n" :: "r"(dst), "l"(src));
}
__device__ __forceinline__ void ldm4(uint32_t (&r)[4], uint32_t addr) {
    asm volatile("ldmatrix.sync.aligned.m8n8.x4.shared.b16 {%0,%1,%2,%3}, [%4];\n"
                 : "=r"(r[0]), "=r"(r[1]), "=r"(r[2]), "=r"(r[3]) : "r"(addr));
}
__device__ __forceinline__ void mma16816(float (&d)[4], const uint32_t (&a)[4],
                                         uint32_t b0, uint32_t b1) {
    asm volatile("mma.sync.aligned.m16n8k16.row.col.f32.f16.f16.f32 "
                 "{%0,%1,%2,%3}, {%4,%5,%6,%7}, {%8,%9}, {%0,%1,%2,%3};\n"
                 : "+f"(d[0]), "+f"(d[1]), "+f"(d[2]), "+f"(d[3])
                 : "r"(a[0]), "r"(a[1]), "r"(a[2]), "r"(a[3]), "r"(b0), "r"(b1));
}
__device__ __forceinline__ float sigf(float x) { return 1.0f / (1.0f + __expf(-x)); }

// split 2 floats into fp16 hi/lo pairs, store packed
__device__ __forceinline__ void split_store2(fp16* hi, fp16* lo, float a, float b) {
    fp16 ha = __float2half_rn(a);
    fp16 hb = __float2half_rn(b);
    *reinterpret_cast<__half2*>(hi) = __halves2half2(ha, hb);
    fp16 la = __float2half_rn(a - __half2float(ha));
    fp16 lb = __float2half_rn(b - __half2float(hb));
    *reinterpret_cast<__half2*>(lo) = __halves2half2(la, lb);
}

// ---------------- weight prep: transpose to [N][K] fp16 ----------------
__global__ void prep_weights(const float* __restrict__ W_in, const float* __restrict__ W_z,
                             const float* __restrict__ W_k, const float* __restrict__ W_v,
                             const float* __restrict__ W_d, const float* __restrict__ W_h) {
    int idx = blockIdx.x * 256 + threadIdx.x;
    if (idx >= 6 * HD * HD) return;
    int mat = idx / (HD * HD);
    int e = idx % (HD * HD);
    int k = e / HD, n = e % HD;
    const float* W;
    fp16* D;
    int dst;
    if (mat == 0) {
        W = W_in; D = g_W_in; dst = n * HD + k;
    } else if (mat <= 4) {
        W = (mat == 1) ? W_z : (mat == 2) ? W_k : (mat == 3) ? W_v : W_d;
        D = g_W_cat; dst = ((mat - 1) * HD + n) * HD + k;
    } else {
        W = W_h; D = g_W_h; dst = n * HD + k;
    }
    D[dst] = __float2half_rn(W[e]);   // W[k][n], coalesced read over n
}

// ---------------- split x into fp16 hi/lo ----------------
__global__ void split_x_kernel(const float* __restrict__ x) {
    int i = blockIdx.x * 256 + threadIdx.x;  // over BATCH*HD/4 float4s
    float4 v = reinterpret_cast<const float4*>(x)[i];
    size_t idx = (size_t)i * 4;
    split_store2(g_x1 + idx, g_x2 + idx, v.x, v.y);
    split_store2(g_x1 + idx + 2, g_x2 + idx + 2, v.z, v.w);
}

// ---------------- split-fp16 GEMM: C[M,N] = A[M,512] @ W[512,N] ----------------
// 2-term: per k-stage load A1,A2,B once; compute A1*B + A2*B (exact A split,
// B single fp16 -> only B-rounding error ~1.4e-4).
#define BM 128
#define BN 128
#define BK 32
#define KST 40                         // padded row stride (fp16) = 80 bytes
#define TILEB (BM * KST * 2)           // 10240 bytes per [128][40] fp16 tile
#define NSTG 16                        // 512 / 32
#define SMEM_DYN (6 * TILEB)           // 2 stages * (A1,A2,B) = 60 KB

template <int WHICH>
__global__ void __launch_bounds__(256, 2) gemm2_kernel() {
    const fp16* A1 = (WHICH == 0) ? g_x1 : (WHICH == 1) ? g_u1 : g_t1;
    const fp16* A2 = (WHICH == 0) ? g_x2 : (WHICH == 1) ? g_u2 : g_t2;
    const fp16* Bp = (WHICH == 0) ? g_W_in : (WHICH == 1) ? g_W_cat : g_W_h;
    float* C = (WHICH == 1) ? g_P : g_pre;
    const int N = (WHICH == 1) ? 4 * HD : HD;

    extern __shared__ __align__(16) char sm[];
    auto tile = [&](int stage, int sel) -> fp16* {    // sel: 0=A1, 1=A2, 2=B
        return reinterpret_cast<fp16*>(sm + (size_t)(stage * 3 + sel) * TILEB);
    };

    const int tid = threadIdx.x;
    const int m0 = blockIdx.y * BM;
    const int n0 = blockIdx.x * BN;
    const int warp = tid >> 5, lane = tid & 31;
    const int wm = (warp >> 1) * 32;  // 4 warps along M
    const int wn = (warp & 1) * 64;   // 2 warps along N

    float acc[2][8][4];
#pragma unroll
    for (int i = 0; i < 2; i++)
#pragma unroll
        for (int j = 0; j < 8; j++)
#pragma unroll
            for (int q = 0; q < 4; q++) acc[i][j][q] = 0.f;

    auto load_stage = [&](int s) {
        const int st = s & 1;
        const int k0 = s * BK;
        fp16* a1 = tile(st, 0);
        fp16* a2 = tile(st, 1);
        fp16* bb = tile(st, 2);
#pragma unroll
        for (int i = 0; i < 2; i++) {
            int c = i * 256 + tid;          // 0..511
            int row = c >> 2;               // 0..127
            int col = (c & 3) * 8;          // fp16 col offset within 32
            uint32_t d = (uint32_t)(row * KST + col) * 2;  // byte offset
            size_t offA = (size_t)(m0 + row) * HD + k0 + col;
            cp16(smem_u32(a1) + d, A1 + offA);
            cp16(smem_u32(a2) + d, A2 + offA);
            size_t offB = (size_t)(n0 + row) * HD + k0 + col;
            cp16(smem_u32(bb) + d, Bp + offB);
        }
        asm volatile("cp.async.commit_group;\n");
    };

    auto compute_pass = [&](const fp16* At, const fp16* Bt) {
#pragma unroll
        for (int kk = 0; kk < BK; kk += 16) {
            uint32_t aF[2][4];
#pragma unroll
            for (int mi = 0; mi < 2; mi++) {
                uint32_t ad = smem_u32(At + (wm + mi * 16 + (lane & 15)) * KST
                                          + kk + ((lane >> 4) << 3));
                ldm4(aF[mi], ad);
            }
            uint32_t bF[4][4];
#pragma unroll
            for (int nb = 0; nb < 4; nb++) {
                uint32_t bd = smem_u32(Bt + (wn + nb * 16 + (lane & 7) + ((lane >> 4) << 3)) * KST
                                          + kk + (((lane >> 3) & 1) << 3));
                ldm4(bF[nb], bd);
            }
#pragma unroll
            for (int mi = 0; mi < 2; mi++)
#pragma unroll
                for (int ni = 0; ni < 8; ni++)
                    mma16816(acc[mi][ni], aF[mi], bF[ni >> 1][(ni & 1) * 2],
                             bF[ni >> 1][(ni & 1) * 2 + 1]);
        }
    };

    load_stage(0);
    load_stage(1);

    for (int s = 0; s < NSTG; ++s) {
        const int st = s & 1;
        if (s == NSTG - 1) asm volatile("cp.async.wait_group 0;\n");
        else               asm volatile("cp.async.wait_group 1;\n");
        __syncthreads();
        compute_pass(tile(st, 0), tile(st, 2));   // A1 * B
        compute_pass(tile(st, 1), tile(st, 2));   // A2 * B
        __syncthreads();
        if (s + 2 < NSTG) load_stage(s + 2);
    }

    // epilogue: write fp32 C
#pragma unroll
    for (int mi = 0; mi < 2; mi++)
#pragma unroll
        for (int ni = 0; ni < 8; ni++) {
            int r = m0 + wm + mi * 16 + (lane >> 2);
            int c = n0 + wn + ni * 8 + (lane & 3) * 2;
            *reinterpret_cast<float2*>(&C[(size_t)r * N + c]) =
                make_float2(acc[mi][ni][0], acc[mi][ni][1]);
            *reinterpret_cast<float2*>(&C[(size_t)(r + 8) * N + c]) =
                make_float2(acc[mi][ni][2], acc[mi][ni][3]);
        }
}

// ---------------- LN over g_pre -> u (fp16 hi/lo) ----------------
__global__ void ln_u_kernel(const float* __restrict__ bias, const float* __restrict__ gamma,
                            const float* __restrict__ beta) {
    int row = blockIdx.x * 8 + (threadIdx.x >> 5);
    int lane = threadIdx.x & 31;
    const float* p = g_pre + (size_t)row * HD;
    float v[16];
    float sm = 0.f, sq = 0.f;
#pragma unroll
    for (int i = 0; i < 4; i++) {
        int c = i * 128 + lane * 4;
        float4 x4 = *reinterpret_cast<const float4*>(p + c);
        float4 b4 = *reinterpret_cast<const float4*>(bias + c);
        float t0 = x4.x + b4.x, t1 = x4.y + b4.y, t2 = x4.z + b4.z, t3 = x4.w + b4.w;
        v[i * 4 + 0] = t0; v[i * 4 + 1] = t1; v[i * 4 + 2] = t2; v[i * 4 + 3] = t3;
        sm += t0 + t1 + t2 + t3;
        sq += t0 * t0 + t1 * t1 + t2 * t2 + t3 * t3;
    }
#pragma unroll
    for (int o = 16; o; o >>= 1) {
        sm += __shfl_xor_sync(0xffffffffu, sm, o);
        sq += __shfl_xor_sync(0xffffffffu, sq, o);
    }
    float mean = sm * (1.f / HD);
    float inv = rsqrtf(fmaxf(sq * (1.f / HD) - mean * mean, 0.f) + 1e-5f);
#pragma unroll
    for (int i = 0; i < 4; i++) {
        int c = i * 128 + lane * 4;
        float4 g4 = *reinterpret_cast<const float4*>(gamma + c);
        float4 b4 = *reinterpret_cast<const float4*>(beta + c);
        float u0 = (v[i * 4 + 0] - mean) * inv * g4.x + b4.x;
        float u1 = (v[i * 4 + 1] - mean) * inv * g4.y + b4.y;
        float u2 = (v[i * 4 + 2] - mean) * inv * g4.z + b4.z;
        float u3 = (v[i * 4 + 3] - mean) * inv * g4.w + b4.w;
        size_t idx = (size_t)row * HD + c;
        split_store2(g_u1 + idx, g_u2 + idx, u0, u1);
        split_store2(g_u1 + idx + 2, g_u2 + idx + 2, u2, u3);
    }
}

// ---------------- epilogue 1: z, s, t ----------------
__global__ void epi1_kernel(const float* __restrict__ s_prev, const float* __restrict__ bz,
                            const float* __restrict__ glz, const float* __restrict__ blz,
                            const float* __restrict__ bk, const float* __restrict__ bv,
                            const float* __restrict__ bd, float* __restrict__ out_s) {
    int row = blockIdx.x * 8 + (threadIdx.x >> 5);
    int lane = threadIdx.x & 31;
    const float* Pr = g_P + (size_t)row * (4 * HD);
    float zp[16];
    float sm = 0.f, sq = 0.f;
#pragma unroll
    for (int i = 0; i < 4; i++) {
        int c = i * 128 + lane * 4;
        float4 z4 = *reinterpret_cast<const float4*>(Pr + c);
        float4 b4 = *reinterpret_cast<const float4*>(bz + c);
        float t0 = z4.x + b4.x, t1 = z4.y + b4.y, t2 = z4.z + b4.z, t3 = z4.w + b4.w;
        zp[i * 4 + 0] = t0; zp[i * 4 + 1] = t1; zp[i * 4 + 2] = t2; zp[i * 4 + 3] = t3;
        sm += t0 + t1 + t2 + t3;
        sq += t0 * t0 + t1 * t1 + t2 * t2 + t3 * t3;
    }
#pragma unroll
    for (int o = 16; o; o >>= 1) {
        sm += __shfl_xor_sync(0xffffffffu, sm, o);
        sq += __shfl_xor_sync(0xffffffffu, sq, o);
    }
    float mean = sm * (1.f / HD);
    float inv = rsqrtf(fmaxf(sq * (1.f / HD) - mean * mean, 0.f) + 1e-5f);
#pragma unroll
    for (int i = 0; i < 4; i++) {
        int c = i * 128 + lane * 4;
        size_t idx = (size_t)row * HD + c;
        float4 g4 = *reinterpret_cast<const float4*>(glz + c);
        float4 bb4 = *reinterpret_cast<const float4*>(blz + c);
        float z0 = sigf((zp[i * 4 + 0] - mean) * inv * g4.x + bb4.x);
        float z1 = sigf((zp[i * 4 + 1] - mean) * inv * g4.y + bb4.y);
        float z2 = sigf((zp[i * 4 + 2] - mean) * inv * g4.z + bb4.z);
        float z3 = sigf((zp[i * 4 + 3] - mean) * inv * g4.w + bb4.w);

        float4 k4 = *reinterpret_cast<const float4*>(Pr + HD + c);
        float4 bk4 = *reinterpret_cast<const float4*>(bk + c);
        float4 v4 = *reinterpret_cast<const float4*>(Pr + 2 * HD + c);
        float4 bv4 = *reinterpret_cast<const float4*>(bv + c);
        float4 d4 = *reinterpret_cast<const float4*>(Pr + 3 * HD + c);
        float4 bd4 = *reinterpret_cast<const float4*>(bd + c);
        float4 sp = *reinterpret_cast<const float4*>(s_prev + idx);

        float kk0 = k4.x + bk4.x, kk1 = k4.y + bk4.y, kk2 = k4.z + bk4.z, kk3 = k4.w + bk4.w;
        float vv0 = v4.x + bv4.x, vv1 = v4.y + bv4.y, vv2 = v4.z + bv4.z, vv3 = v4.w + bv4.w;
        float dc0 = sigf(d4.x + bd4.x), dc1 = sigf(d4.y + bd4.y);
        float dc2 = sigf(d4.z + bd4.z), dc3 = sigf(d4.w + bd4.w);
        float s0 = dc0 * sp.x + kk0 * vv0;
        float s1 = dc1 * sp.y + kk1 * vv1;
        float s2 = dc2 * sp.z + kk2 * vv2;
        float s3 = dc3 * sp.w + kk3 * vv3;
        *reinterpret_cast<float4*>(out_s + idx) = make_float4(s0, s1, s2, s3);

        __half2 uh0 = *reinterpret_cast<const __half2*>(g_u1 + idx);
        __half2 ul0 = *reinterpret_cast<const __half2*>(g_u2 + idx);
        __half2 uh1 = *reinterpret_cast<const __half2*>(g_u1 + idx + 2);
        __half2 ul1 = *reinterpret_cast<const __half2*>(g_u2 + idx + 2);
        float u0 = __half2float(uh0.x) + __half2float(ul0.x);
        float u1 = __half2float(uh0.y) + __half2float(ul0.y);
        float u2 = __half2float(uh1.x) + __half2float(ul1.x);
        float u3 = __half2float(uh1.y) + __half2float(ul1.y);
        split_store2(g_t1 + idx, g_t2 + idx, u0 + s0, u1 + s1);
        split_store2(g_t1 + idx + 2, g_t2 + idx + 2, u2 + s2, u3 + s3);
        *reinterpret_cast<float4*>(&g_z[idx]) = make_float4(z0, z1, z2, z3);
    }
}

// ---------------- epilogue 2: h ----------------
__global__ void epi2_kernel(const float* __restrict__ h_prev, const float* __restrict__ bh,
                            const float* __restrict__ glh, const float* __restrict__ blh,
                            float* __restrict__ out_h) {
    int row = blockIdx.x * 8 + (threadIdx.x >> 5);
    int lane = threadIdx.x & 31;
    const float* p = g_pre + (size_t)row * HD;
    float v[16];
    float sm = 0.f, sq = 0.f;
#pragma unroll
    for (int i = 0; i < 4; i++) {
        int c = i * 128 + lane * 4;
        float4 x4 = *reinterpret_cast<const float4*>(p + c);
        float4 b4 = *reinterpret_cast<const float4*>(bh + c);
        float t0 = x4.x + b4.x, t1 = x4.y + b4.y, t2 = x4.z + b4.z, t3 = x4.w + b4.w;
        v[i * 4 + 0] = t0; v[i * 4 + 1] = t1; v[i * 4 + 2] = t2; v[i * 4 + 3] = t3;
        sm += t0 + t1 + t2 + t3;
        sq += t0 * t0 + t1 * t1 + t2 * t2 + t3 * t3;
    }
#pragma unroll
    for (int o = 16; o; o >>= 1) {
        sm += __shfl_xor_sync(0xffffffffu, sm, o);
        sq += __shfl_xor_sync(0xffffffffu, sq, o);
    }
    float mean = sm * (1.f / HD);
    float inv = rsqrtf(fmaxf(sq * (1.f / HD) - mean * mean, 0.f) + 1e-5f);
#pragma unroll
    for (int i = 0; i < 4; i++) {
        int c = i * 128 + lane * 4;
        size_t idx = (size_t)row * HD + c;
        float4 g4 = *reinterpret_cast<const float4*>(glh + c);
        float4 b4 = *reinterpret_cast<const float4*>(blh + c);
        float c0 = tanhf((v[i * 4 + 0] - mean) * inv * g4.x + b4.x);
        float c1 = tanhf((v[i * 4 + 1] - mean) * inv * g4.y + b4.y);
        float c2 = tanhf((v[i * 4 + 2] - mean) * inv * g4.z + b4.z);
        float c3 = tanhf((v[i * 4 + 3] - mean) * inv * g4.w + b4.w);
        float4 z4 = *reinterpret_cast<const float4*>(&g_z[idx]);
        float4 hp = *reinterpret_cast<const float4*>(h_prev + idx);
        float h0 = (1.f - z4.x) * c0 + z4.x * hp.x;
        float h1 = (1.f - z4.y) * c1 + z4.y * hp.y;
        float h2 = (1.f - z4.z) * c2 + z4.z * hp.z;
        float h3 = (1.f - z4.w) * c3 + z4.w * hp.w;
        *reinterpret_cast<float4*>(out_h + idx) = make_float4(h0, h1, h2, h3);
    }
}

// ---------------- launch ----------------
extern "C" void kernel_launch(void* const* d_in, const int* in_sizes, int n_in,
                              void* d_out, int out_size) {
    const float* x       = (const float*)d_in[0];
    const float* h_prev  = (const float*)d_in[1];
    const float* s_prev  = (const float*)d_in[2];
    const float* W_in    = (const float*)d_in[3];
    const float* b_in    = (const float*)d_in[4];
    const float* g_ln_in = (const float*)d_in[5];
    const float* b_ln_in = (const float*)d_in[6];
    const float* g_ln_z  = (const float*)d_in[9];
    const float* b_ln_z  = (const float*)d_in[10];
    const float* g_ln_h  = (const float*)d_in[11];
    const float* b_ln_h  = (const float*)d_in[12];
    const float* W_z     = (const float*)d_in[15];
    const float* b_z     = (const float*)d_in[16];
    const float* W_k     = (const float*)d_in[17];
    const float* b_k     = (const float*)d_in[18];
    const float* W_v     = (const float*)d_in[19];
    const float* b_v     = (const float*)d_in[20];
    const float* W_h     = (const float*)d_in[21];
    const float* b_h     = (const float*)d_in[22];
    const float* W_d     = (const float*)d_in[23];
    const float* b_d     = (const float*)d_in[24];

    float* out_h = (float*)d_out;
    float* out_s = out_h + (size_t)BATCH * HD;

    cudaFuncSetAttribute(gemm2_kernel<0>, cudaFuncAttributeMaxDynamicSharedMemorySize, SMEM_DYN);
    cudaFuncSetAttribute(gemm2_kernel<1>, cudaFuncAttributeMaxDynamicSharedMemorySize, SMEM_DYN);
    cudaFuncSetAttribute(gemm2_kernel<2>, cudaFuncAttributeMaxDynamicSharedMemorySize, SMEM_DYN);

    prep_weights<<<(6 * HD * HD + 255) / 256, 256>>>(W_in, W_z, W_k, W_v, W_d, W_h);
    split_x_kernel<<<BATCH * HD / 4 / 256, 256>>>(x);

    gemm2_kernel<0><<<dim3(HD / BN, BATCH / BM), 256, SMEM_DYN>>>();
    ln_u_kernel<<<BATCH / 8, 256>>>(b_in, g_ln_in, b_ln_in);

    gemm2_kernel<1><<<dim3(4 * HD / BN, BATCH / BM), 256, SMEM_DYN>>>();
    epi1_kernel<<<BATCH / 8, 256>>>(s_prev, b_z, g_ln_z, b_ln_z, b_k, b_v, b_d, out_s);

    gemm2_kernel<2><<<dim3(HD / BN, BATCH / BM), 256, SMEM_DYN>>>();
    epi2_kernel<<<BATCH / 8, 256>>>(h_prev, b_h, g_ln_h, b_ln_h, out_h);
}